// round 2
// baseline (speedup 1.0000x reference)
#include <cuda_runtime.h>
#include <cuda_bf16.h>
#include <cstdint>

// Problem constants (fixed shapes from reference setup_inputs)
#define BQ   32             // batch
#define NB   300            // boxes per batch
#define HH   1024
#define WW   1024
#define RPC  16             // rows per CTA
#define CHUNKS (HH / RPC)   // 64 row-chunks per image
#define NTH  256            // threads per CTA (8 warps)
#define NBOX_TOTAL (BQ * NB)   // 9600

// ---------------- device scratch (no allocations allowed) ----------------
__device__ int4  g_box[NBOX_TOTAL];                    // {x1, y1, x2, y2}; empty y-range if invalid
__device__ float g_scl[NBOX_TOTAL];                    // conf/area if valid else 0
__device__ float g_part[(size_t)BQ * CHUNKS * NB];     // per (batch, chunk, box) partial sums

// ---------------- phase 0: box preprocessing ----------------
__global__ void prep_kernel(const float* __restrict__ boxes,
                            const float* __restrict__ conf) {
    int i = blockIdx.x * blockDim.x + threadIdx.x;
    if (i >= NBOX_TOTAL) return;
    float4 bx = reinterpret_cast<const float4*>(boxes)[i];
    float cx = bx.x, cy = bx.y, w = bx.z, h = bx.w;

    // matches reference: clip(trunc(v).astype(int32), 0, dim-1)
    float fx1 = truncf((cx - 0.5f * w) * (float)WW);
    float fx2 = truncf((cx + 0.5f * w) * (float)WW);
    float fy1 = truncf((cy - 0.5f * h) * (float)HH);
    float fy2 = truncf((cy + 0.5f * h) * (float)HH);
    int x1 = min(max((int)fx1, 0), WW - 1);
    int x2 = min(max((int)fx2, 0), WW - 1);
    int y1 = min(max((int)fy1, 0), HH - 1);
    int y2 = min(max((int)fy2, 0), HH - 1);

    float c = conf[i];
    bool valid = (c >= 0.3f) && (x2 > x1) && (y2 > y1);
    float area = (float)((y2 - y1) * (x2 - x1));
    g_scl[i] = valid ? (c / area) : 0.0f;
    if (!valid) { y1 = 0; y2 = 0; }   // empty y-range: phase-1 accumulates nothing
    g_box[i] = make_int4(x1, y1, x2, y2);
}

// ---------------- phase 1: fused row-scan + box rectangle sums ----------------
// grid: (CHUNKS, BQ); block: NTH threads. Each CTA handles RPC rows of one image.
// Reads classes 1 and 2 exactly once from HBM; nothing else touches DRAM.
__global__ void __launch_bounds__(NTH)
rows_kernel(const float* __restrict__ seg) {
    __shared__ float ps[WW];              // exclusive prefix of diff for current row
    __shared__ float wtot[NTH / 32];      // per-warp totals

    const int b     = blockIdx.y;
    const int chunk = blockIdx.x;
    const int t     = threadIdx.x;
    const int warp  = t >> 5;
    const int lane  = t & 31;

    const size_t HW = (size_t)HH * WW;
    const float* c1 = seg + ((size_t)b * 3 + 1) * HW + (size_t)(chunk * RPC) * WW;  // driveway
    const float* c2 = c1 + HW;                                                      // footpath

    // Box ownership: thread t owns box t, plus box t+256 when it exists (NB=300).
    const int4 B0 = g_box[b * NB + t];
    const bool has1 = (t + NTH) < NB;
    int4 B1 = make_int4(0, 0, 0, 0);
    if (has1) B1 = g_box[b * NB + t + NTH];

    float acc0 = 0.0f, acc1 = 0.0f;

    // prefetch row 0
    float4 a1 = reinterpret_cast<const float4*>(c1)[t];
    float4 a2 = reinterpret_cast<const float4*>(c2)[t];

    #pragma unroll 1
    for (int r = 0; r < RPC; r++) {
        float4 v1 = a1, v2 = a2;
        if (r + 1 < RPC) {   // prefetch next row while we scan this one
            a1 = reinterpret_cast<const float4*>(c1 + (size_t)(r + 1) * WW)[t];
            a2 = reinterpret_cast<const float4*>(c2 + (size_t)(r + 1) * WW)[t];
        }

        // diff = footpath - driveway
        float d0 = v2.x - v1.x, d1 = v2.y - v1.y, d2 = v2.z - v1.z, d3 = v2.w - v1.w;
        // thread-local inclusive prefix over 4 elements
        float s0 = d0, s1 = s0 + d1, s2 = s1 + d2, s3 = s2 + d3;
        float tot = s3;

        // warp inclusive scan of per-thread totals
        float inc = tot;
        #pragma unroll
        for (int o = 1; o < 32; o <<= 1) {
            float n = __shfl_up_sync(0xFFFFFFFFu, inc, o);
            if (lane >= o) inc += n;
        }
        float texcl = inc - tot;
        if (lane == 31) wtot[warp] = inc;
        __syncthreads();   // fences prev-iter ps reads vs upcoming ps writes, and wtot write

        float base = texcl;
        #pragma unroll
        for (int wI = 0; wI < NTH / 32; wI++)
            if (wI < warp) base += wtot[wI];

        const int x4 = t << 2;
        ps[x4 + 0] = base;
        ps[x4 + 1] = base + s0;
        ps[x4 + 2] = base + s1;
        ps[x4 + 3] = base + s2;
        __syncthreads();

        // accumulate boxes covering this row: sum over cols [x1, x2) == ps[x2]-ps[x1]
        const int y = chunk * RPC + r;
        if (y >= B0.y && y < B0.w) acc0 += ps[B0.z] - ps[B0.x];
        if (has1 && y >= B1.y && y < B1.w) acc1 += ps[B1.z] - ps[B1.x];
    }

    float* outp = g_part + ((size_t)b * CHUNKS + chunk) * NB;
    outp[t] = acc0;
    if (has1) outp[t + NTH] = acc1;
}

// ---------------- phase 2: single-block combine + full reduce ----------------
// 9600 boxes, 64 chunk-partials each (2.45 MB, L2-resident). One CTA of 1024
// threads grid-strides boxes, then block-reduces to the scalar output.
__global__ void __launch_bounds__(1024)
combine_final_kernel(float* __restrict__ out) {
    float v = 0.0f;
    for (int i = threadIdx.x; i < NBOX_TOTAL; i += 1024) {
        const int b = i / NB, n = i % NB;
        const float* p = g_part + (size_t)b * CHUNKS * NB + n;
        float r0 = 0.f, r1 = 0.f, r2 = 0.f, r3 = 0.f;
        #pragma unroll
        for (int c = 0; c < CHUNKS; c += 4) {
            r0 += p[(size_t)(c + 0) * NB];
            r1 += p[(size_t)(c + 1) * NB];
            r2 += p[(size_t)(c + 2) * NB];
            r3 += p[(size_t)(c + 3) * NB];
        }
        float S = (r0 + r1) + (r2 + r3);
        v += fmaxf(S, 0.0f) * g_scl[i];   // relu(S/area)*conf, fused
    }
    // block reduction
    __shared__ float sm[32];
    #pragma unroll
    for (int o = 16; o > 0; o >>= 1) v += __shfl_down_sync(0xFFFFFFFFu, v, o);
    if ((threadIdx.x & 31) == 0) sm[threadIdx.x >> 5] = v;
    __syncthreads();
    if (threadIdx.x < 32) {
        float w = sm[threadIdx.x];
        #pragma unroll
        for (int o = 16; o > 0; o >>= 1) w += __shfl_down_sync(0xFFFFFFFFu, w, o);
        if (threadIdx.x == 0) out[0] = w * (1.0f / (float)NBOX_TOTAL);
    }
}

// ---------------- launch ----------------
extern "C" void kernel_launch(void* const* d_in, const int* in_sizes, int n_in,
                              void* d_out, int out_size) {
    const float* det_boxes = (const float*)d_in[0];   // (32,300,4)
    const float* det_conf  = (const float*)d_in[1];   // (32,300)
    const float* seg       = (const float*)d_in[2];   // (32,3,1024,1024)
    float* out = (float*)d_out;

    prep_kernel<<<(NBOX_TOTAL + NTH - 1) / NTH, NTH>>>(det_boxes, det_conf);

    dim3 grid(CHUNKS, BQ);
    rows_kernel<<<grid, NTH>>>(seg);

    combine_final_kernel<<<1, 1024>>>(out);
}

// round 5
// speedup vs baseline: 1.3109x; 1.3109x over previous
#include <cuda_runtime.h>
#include <cuda_bf16.h>
#include <cstdint>

// Fixed shapes from reference setup_inputs
#define BQ   32             // batch
#define NB   300            // boxes per batch
#define HH   1024
#define WW   1024
#define RPC  32             // rows per CTA
#define CHUNKS (HH / RPC)   // 32 row-chunks per image
#define NTH  256            // threads per CTA (8 warps)
#define NBOX_TOTAL (BQ * NB)   // 9600

// ---------------- device scratch (no allocations allowed) ----------------
__device__ float g_part[(size_t)BQ * CHUNKS * NB];   // per (batch, chunk, box) partials: 1.2 MB
__device__ float g_bsum[BQ];                         // per-batch sums

// Box edge computation — matches reference: clip(trunc(v).astype(int32), 0, dim-1)
__device__ __forceinline__ int4 make_box(float4 bx, float c) {
    float cx = bx.x, cy = bx.y, w = bx.z, h = bx.w;
    int x1 = min(max((int)truncf((cx - 0.5f * w) * (float)WW), 0), WW - 1);
    int x2 = min(max((int)truncf((cx + 0.5f * w) * (float)WW), 0), WW - 1);
    int y1 = min(max((int)truncf((cy - 0.5f * h) * (float)HH), 0), HH - 1);
    int y2 = min(max((int)truncf((cy + 0.5f * h) * (float)HH), 0), HH - 1);
    bool valid = (c >= 0.3f) && (x2 > x1) && (y2 > y1);
    if (!valid) { y1 = 0; y2 = 0; }   // empty y-range: accumulates nothing
    return make_int4(x1, y1, x2, y2);
}

// ---------------- phase 1: fused prep + row-scan + box rectangle sums ----------------
// grid: (CHUNKS, BQ) = 1024 CTAs -> single wave at 8 CTAs/SM. Each CTA: 32 rows
// of one image, 2 rows per iteration (two interleaved scans -> ILP 2, half the
// barriers per byte). Reads classes 1 and 2 exactly once from HBM.
__global__ void __launch_bounds__(NTH)
rows_kernel(const float* __restrict__ seg,
            const float* __restrict__ boxes,
            const float* __restrict__ conf) {
    __shared__ float ps[2][WW];          // exclusive prefix of diff, rows r and r+1
    __shared__ float wtot[2][NTH / 32];  // per-warp totals, both rows
    __shared__ int4  sbox[NB];           // this batch's boxes

    const int b     = blockIdx.y;
    const int chunk = blockIdx.x;
    const int t     = threadIdx.x;
    const int warp  = t >> 5;
    const int lane  = t & 31;

    // ---- inline prep: build the box table for this batch (redundant per CTA, trivial) ----
    for (int i = t; i < NB; i += NTH) {
        float4 bx = reinterpret_cast<const float4*>(boxes)[b * NB + i];
        sbox[i] = make_box(bx, conf[b * NB + i]);
    }
    __syncthreads();

    // Box ownership: thread t owns box t, plus t+256 when it exists (NB=300).
    const int4 B0 = sbox[t];
    const bool has1 = (t + NTH) < NB;
    const int4 B1 = has1 ? sbox[t + NTH] : make_int4(0, 0, 0, 0);

    const size_t HW = (size_t)HH * WW;
    const float4* f1 = reinterpret_cast<const float4*>(
        seg + ((size_t)b * 3 + 1) * HW + (size_t)(chunk * RPC) * WW);  // driveway
    const float4* f2 = reinterpret_cast<const float4*>(
        seg + ((size_t)b * 3 + 2) * HW + (size_t)(chunk * RPC) * WW);  // footpath
    const int RSTRIDE = WW / 4;   // 256 float4 per row

    float acc0 = 0.0f, acc1 = 0.0f;

    // prefetch rows 0,1 for both classes
    float4 n1a = f1[t], n1b = f1[RSTRIDE + t];
    float4 n2a = f2[t], n2b = f2[RSTRIDE + t];

    #pragma unroll 1
    for (int r = 0; r < RPC; r += 2) {
        float4 v1a = n1a, v1b = n1b, v2a = n2a, v2b = n2b;
        if (r + 2 < RPC) {   // prefetch next pair while scanning this one
            n1a = f1[(r + 2) * RSTRIDE + t];
            n1b = f1[(r + 3) * RSTRIDE + t];
            n2a = f2[(r + 2) * RSTRIDE + t];
            n2b = f2[(r + 3) * RSTRIDE + t];
        }

        // diff = footpath - driveway; thread-local inclusive prefix over 4 elems (x2 rows)
        float a0 = v2a.x - v1a.x, a1 = v2a.y - v1a.y, a2 = v2a.z - v1a.z, a3 = v2a.w - v1a.w;
        float b0 = v2b.x - v1b.x, b1 = v2b.y - v1b.y, b2 = v2b.z - v1b.z, b3 = v2b.w - v1b.w;
        float sA0 = a0, sA1 = sA0 + a1, sA2 = sA1 + a2, sA3 = sA2 + a3;
        float sB0 = b0, sB1 = sB0 + b1, sB2 = sB1 + b2, sB3 = sB2 + b3;
        float totA = sA3, totB = sB3;

        // two interleaved warp inclusive scans (independent SHFL chains)
        float incA = totA, incB = totB;
        #pragma unroll
        for (int o = 1; o < 32; o <<= 1) {
            float nA = __shfl_up_sync(0xFFFFFFFFu, incA, o);
            float nB = __shfl_up_sync(0xFFFFFFFFu, incB, o);
            if (lane >= o) { incA += nA; incB += nB; }
        }
        float exA = incA - totA, exB = incB - totB;
        if (lane == 31) { wtot[0][warp] = incA; wtot[1][warp] = incB; }
        __syncthreads();   // wtot published; also fences prev-iter ps reads vs writes below

        float baseA = exA, baseB = exB;
        #pragma unroll
        for (int wI = 0; wI < NTH / 32; wI++)
            if (wI < warp) { baseA += wtot[0][wI]; baseB += wtot[1][wI]; }

        const int x4 = t << 2;
        ps[0][x4 + 0] = baseA;          ps[1][x4 + 0] = baseB;
        ps[0][x4 + 1] = baseA + sA0;    ps[1][x4 + 1] = baseB + sB0;
        ps[0][x4 + 2] = baseA + sA1;    ps[1][x4 + 2] = baseB + sB1;
        ps[0][x4 + 3] = baseA + sA2;    ps[1][x4 + 3] = baseB + sB2;
        __syncthreads();

        // box accumulation for both rows: sum over cols [x1, x2) = ps[x2]-ps[x1]
        const int y0 = chunk * RPC + r;
        const int y1r = y0 + 1;
        if (y0  >= B0.y && y0  < B0.w) acc0 += ps[0][B0.z] - ps[0][B0.x];
        if (y1r >= B0.y && y1r < B0.w) acc0 += ps[1][B0.z] - ps[1][B0.x];
        if (has1) {
            if (y0  >= B1.y && y0  < B1.w) acc1 += ps[0][B1.z] - ps[0][B1.x];
            if (y1r >= B1.y && y1r < B1.w) acc1 += ps[1][B1.z] - ps[1][B1.x];
        }
    }

    float* outp = g_part + ((size_t)b * CHUNKS + chunk) * NB;
    outp[t] = acc0;
    if (has1) outp[t + NTH] = acc1;
}

// ---------------- phase 2: per-batch combine (32 CTAs, deterministic) ----------------
// CTA b reduces its batch's 300 boxes x 32 chunk-partials (38 KB, L2-resident).
__global__ void __launch_bounds__(NTH)
combine_kernel(const float* __restrict__ boxes,
               const float* __restrict__ conf) {
    const int b = blockIdx.x;
    float v = 0.0f;
    for (int n = threadIdx.x; n < NB; n += NTH) {
        const int i = b * NB + n;
        // recompute scale = valid ? conf/area : 0
        float4 bx = reinterpret_cast<const float4*>(boxes)[i];
        float c = conf[i];
        float cx = bx.x, cy = bx.y, w = bx.z, h = bx.w;
        int x1 = min(max((int)truncf((cx - 0.5f * w) * (float)WW), 0), WW - 1);
        int x2 = min(max((int)truncf((cx + 0.5f * w) * (float)WW), 0), WW - 1);
        int y1 = min(max((int)truncf((cy - 0.5f * h) * (float)HH), 0), HH - 1);
        int y2 = min(max((int)truncf((cy + 0.5f * h) * (float)HH), 0), HH - 1);
        bool valid = (c >= 0.3f) && (x2 > x1) && (y2 > y1);
        float area = (float)((y2 - y1) * (x2 - x1));
        float scl = valid ? (c / area) : 0.0f;

        const float* p = g_part + (size_t)b * CHUNKS * NB + n;
        float r0 = 0.f, r1 = 0.f, r2 = 0.f, r3 = 0.f;
        #pragma unroll
        for (int cc = 0; cc < CHUNKS; cc += 4) {
            r0 += p[(size_t)(cc + 0) * NB];
            r1 += p[(size_t)(cc + 1) * NB];
            r2 += p[(size_t)(cc + 2) * NB];
            r3 += p[(size_t)(cc + 3) * NB];
        }
        float S = (r0 + r1) + (r2 + r3);
        v += fmaxf(S, 0.0f) * scl;
    }
    // block reduction -> per-batch sum (fixed order, deterministic)
    __shared__ float sm[NTH / 32];
    #pragma unroll
    for (int o = 16; o > 0; o >>= 1) v += __shfl_down_sync(0xFFFFFFFFu, v, o);
    if ((threadIdx.x & 31) == 0) sm[threadIdx.x >> 5] = v;
    __syncthreads();
    if (threadIdx.x < 32) {
        float w = (threadIdx.x < NTH / 32) ? sm[threadIdx.x] : 0.0f;
        #pragma unroll
        for (int o = 4; o > 0; o >>= 1) w += __shfl_down_sync(0xFFFFFFFFu, w, o);
        if (threadIdx.x == 0) g_bsum[b] = w;
    }
}

// ---------------- phase 3: final scalar ----------------
__global__ void final_kernel(float* __restrict__ out) {
    int t = threadIdx.x;   // 32 threads
    float v = g_bsum[t];
    #pragma unroll
    for (int o = 16; o > 0; o >>= 1) v += __shfl_down_sync(0xFFFFFFFFu, v, o);
    if (t == 0) out[0] = v * (1.0f / (float)NBOX_TOTAL);
}

// ---------------- launch ----------------
extern "C" void kernel_launch(void* const* d_in, const int* in_sizes, int n_in,
                              void* d_out, int out_size) {
    const float* det_boxes = (const float*)d_in[0];   // (32,300,4)
    const float* det_conf  = (const float*)d_in[1];   // (32,300)
    const float* seg       = (const float*)d_in[2];   // (32,3,1024,1024)
    float* out = (float*)d_out;

    dim3 grid(CHUNKS, BQ);
    rows_kernel<<<grid, NTH>>>(seg, det_boxes, det_conf);
    combine_kernel<<<BQ, NTH>>>(det_boxes, det_conf);
    final_kernel<<<1, 32>>>(out);
}

// round 7
// speedup vs baseline: 1.5195x; 1.1591x over previous
#include <cuda_runtime.h>
#include <cuda_bf16.h>
#include <cstdint>

// Fixed shapes from reference setup_inputs
#define BQ   32             // batch
#define NB   300            // boxes per batch
#define HH   1024
#define WW   1024
#define RPC  64             // rows per CTA
#define CHUNKS (HH / RPC)   // 16 row-chunks per image
#define NTH  256            // threads per CTA (8 warps)
#define NBOX_TOTAL (BQ * NB)   // 9600

// ---------------- device scratch (no allocations allowed) ----------------
__device__ float g_part[(size_t)BQ * CHUNKS * NB];   // per (batch, chunk, box) partials: 600 KB
__device__ float g_bsum[BQ];                         // per-batch sums

// Box edge computation — matches reference: clip(trunc(v).astype(int32), 0, dim-1)
__device__ __forceinline__ int4 make_box(float4 bx, float c) {
    float cx = bx.x, cy = bx.y, w = bx.z, h = bx.w;
    int x1 = min(max((int)truncf((cx - 0.5f * w) * (float)WW), 0), WW - 1);
    int x2 = min(max((int)truncf((cx + 0.5f * w) * (float)WW), 0), WW - 1);
    int y1 = min(max((int)truncf((cy - 0.5f * h) * (float)HH), 0), HH - 1);
    int y2 = min(max((int)truncf((cy + 0.5f * h) * (float)HH), 0), HH - 1);
    bool valid = (c >= 0.3f) && (x2 > x1) && (y2 > y1);
    if (!valid) { y1 = 0; y2 = 0; }   // empty y-range: accumulates nothing
    return make_int4(x1, y1, x2, y2);
}

// ---------------- phase 1: fused prep + row-scan + box rectangle sums ----------------
// grid: (CHUNKS, BQ) = 512 CTAs; regs pinned for 4 CTAs/SM -> 512 <= 592 =>
// SINGLE WAVE. Each CTA: 64 rows of one image, 2 rows per iteration (two
// interleaved scans). Reads classes 1 and 2 exactly once from HBM.
__global__ void __launch_bounds__(NTH, 4)
rows_kernel(const float* __restrict__ seg,
            const float* __restrict__ boxes,
            const float* __restrict__ conf) {
    __shared__ float ps[2][WW];          // exclusive prefix of diff, rows r and r+1
    __shared__ float wtot[2][NTH / 32];  // per-warp totals, both rows
    __shared__ int4  sbox[NB];           // this batch's boxes

    const int b     = blockIdx.y;
    const int chunk = blockIdx.x;
    const int t     = threadIdx.x;
    const int warp  = t >> 5;
    const int lane  = t & 31;

    // ---- inline prep: build the box table for this batch (redundant per CTA, trivial) ----
    for (int i = t; i < NB; i += NTH) {
        float4 bx = reinterpret_cast<const float4*>(boxes)[b * NB + i];
        sbox[i] = make_box(bx, conf[b * NB + i]);
    }
    __syncthreads();

    // Box ownership: thread t owns box t, plus t+256 when it exists (NB=300).
    const int4 B0 = sbox[t];
    const bool has1 = (t + NTH) < NB;
    const int4 B1 = has1 ? sbox[t + NTH] : make_int4(0, 0, 0, 0);

    const size_t HW = (size_t)HH * WW;
    const float4* f1 = reinterpret_cast<const float4*>(
        seg + ((size_t)b * 3 + 1) * HW + (size_t)(chunk * RPC) * WW);  // driveway
    const float4* f2 = reinterpret_cast<const float4*>(
        seg + ((size_t)b * 3 + 2) * HW + (size_t)(chunk * RPC) * WW);  // footpath
    const int RSTRIDE = WW / 4;   // 256 float4 per row

    float acc0 = 0.0f, acc1 = 0.0f;

    // prefetch rows 0,1 for both classes
    float4 n1a = f1[t], n1b = f1[RSTRIDE + t];
    float4 n2a = f2[t], n2b = f2[RSTRIDE + t];

    #pragma unroll 1
    for (int r = 0; r < RPC; r += 2) {
        float4 v1a = n1a, v1b = n1b, v2a = n2a, v2b = n2b;
        if (r + 2 < RPC) {   // prefetch next pair while scanning this one
            n1a = f1[(r + 2) * RSTRIDE + t];
            n1b = f1[(r + 3) * RSTRIDE + t];
            n2a = f2[(r + 2) * RSTRIDE + t];
            n2b = f2[(r + 3) * RSTRIDE + t];
        }

        // diff = footpath - driveway; thread-local inclusive prefix over 4 elems (x2 rows)
        float a0 = v2a.x - v1a.x, a1 = v2a.y - v1a.y, a2 = v2a.z - v1a.z, a3 = v2a.w - v1a.w;
        float b0 = v2b.x - v1b.x, b1 = v2b.y - v1b.y, b2 = v2b.z - v1b.z, b3 = v2b.w - v1b.w;
        float sA0 = a0, sA1 = sA0 + a1, sA2 = sA1 + a2, sA3 = sA2 + a3;
        float sB0 = b0, sB1 = sB0 + b1, sB2 = sB1 + b2, sB3 = sB2 + b3;
        float totA = sA3, totB = sB3;

        // two interleaved warp inclusive scans (independent SHFL chains)
        float incA = totA, incB = totB;
        #pragma unroll
        for (int o = 1; o < 32; o <<= 1) {
            float nA = __shfl_up_sync(0xFFFFFFFFu, incA, o);
            float nB = __shfl_up_sync(0xFFFFFFFFu, incB, o);
            if (lane >= o) { incA += nA; incB += nB; }
        }
        float exA = incA - totA, exB = incB - totB;
        if (lane == 31) { wtot[0][warp] = incA; wtot[1][warp] = incB; }
        __syncthreads();   // wtot published; also fences prev-iter ps reads vs writes below

        float baseA = exA, baseB = exB;
        #pragma unroll
        for (int wI = 0; wI < NTH / 32; wI++)
            if (wI < warp) { baseA += wtot[0][wI]; baseB += wtot[1][wI]; }

        // conflict-free vectorized ps publication (one STS.128 per row per thread)
        const int x4 = t << 2;
        *reinterpret_cast<float4*>(&ps[0][x4]) =
            make_float4(baseA, baseA + sA0, baseA + sA1, baseA + sA2);
        *reinterpret_cast<float4*>(&ps[1][x4]) =
            make_float4(baseB, baseB + sB0, baseB + sB1, baseB + sB2);
        __syncthreads();

        // box accumulation for both rows: sum over cols [x1, x2) = ps[x2]-ps[x1]
        const int y0 = chunk * RPC + r;
        const int y1r = y0 + 1;
        if (y0  >= B0.y && y0  < B0.w) acc0 += ps[0][B0.z] - ps[0][B0.x];
        if (y1r >= B0.y && y1r < B0.w) acc0 += ps[1][B0.z] - ps[1][B0.x];
        if (has1) {
            if (y0  >= B1.y && y0  < B1.w) acc1 += ps[0][B1.z] - ps[0][B1.x];
            if (y1r >= B1.y && y1r < B1.w) acc1 += ps[1][B1.z] - ps[1][B1.x];
        }
    }

    float* outp = g_part + ((size_t)b * CHUNKS + chunk) * NB;
    outp[t] = acc0;
    if (has1) outp[t + NTH] = acc1;
}

// ---------------- phase 2: per-batch combine (32 CTAs, deterministic) ----------------
// CTA b reduces its batch's 300 boxes x 16 chunk-partials (19 KB, L2-resident).
__global__ void __launch_bounds__(NTH)
combine_kernel(const float* __restrict__ boxes,
               const float* __restrict__ conf) {
    const int b = blockIdx.x;
    float v = 0.0f;
    for (int n = threadIdx.x; n < NB; n += NTH) {
        const int i = b * NB + n;
        // recompute scale = valid ? conf/area : 0
        float4 bx = reinterpret_cast<const float4*>(boxes)[i];
        float c = conf[i];
        float cx = bx.x, cy = bx.y, w = bx.z, h = bx.w;
        int x1 = min(max((int)truncf((cx - 0.5f * w) * (float)WW), 0), WW - 1);
        int x2 = min(max((int)truncf((cx + 0.5f * w) * (float)WW), 0), WW - 1);
        int y1 = min(max((int)truncf((cy - 0.5f * h) * (float)HH), 0), HH - 1);
        int y2 = min(max((int)truncf((cy + 0.5f * h) * (float)HH), 0), HH - 1);
        bool valid = (c >= 0.3f) && (x2 > x1) && (y2 > y1);
        float area = (float)((y2 - y1) * (x2 - x1));
        float scl = valid ? (c / area) : 0.0f;

        const float* p = g_part + (size_t)b * CHUNKS * NB + n;
        float r0 = 0.f, r1 = 0.f, r2 = 0.f, r3 = 0.f;
        #pragma unroll
        for (int cc = 0; cc < CHUNKS; cc += 4) {
            r0 += p[(size_t)(cc + 0) * NB];
            r1 += p[(size_t)(cc + 1) * NB];
            r2 += p[(size_t)(cc + 2) * NB];
            r3 += p[(size_t)(cc + 3) * NB];
        }
        float S = (r0 + r1) + (r2 + r3);
        v += fmaxf(S, 0.0f) * scl;
    }
    // block reduction -> per-batch sum (fixed order, deterministic)
    __shared__ float sm[NTH / 32];
    #pragma unroll
    for (int o = 16; o > 0; o >>= 1) v += __shfl_down_sync(0xFFFFFFFFu, v, o);
    if ((threadIdx.x & 31) == 0) sm[threadIdx.x >> 5] = v;
    __syncthreads();
    if (threadIdx.x < 32) {
        float w = (threadIdx.x < NTH / 32) ? sm[threadIdx.x] : 0.0f;
        #pragma unroll
        for (int o = 4; o > 0; o >>= 1) w += __shfl_down_sync(0xFFFFFFFFu, w, o);
        if (threadIdx.x == 0) g_bsum[b] = w;
    }
}

// ---------------- phase 3: final scalar ----------------
__global__ void final_kernel(float* __restrict__ out) {
    int t = threadIdx.x;   // 32 threads
    float v = g_bsum[t];
    #pragma unroll
    for (int o = 16; o > 0; o >>= 1) v += __shfl_down_sync(0xFFFFFFFFu, v, o);
    if (t == 0) out[0] = v * (1.0f / (float)NBOX_TOTAL);
}

// ---------------- launch ----------------
extern "C" void kernel_launch(void* const* d_in, const int* in_sizes, int n_in,
                              void* d_out, int out_size) {
    const float* det_boxes = (const float*)d_in[0];   // (32,300,4)
    const float* det_conf  = (const float*)d_in[1];   // (32,300)
    const float* seg       = (const float*)d_in[2];   // (32,3,1024,1024)
    float* out = (float*)d_out;

    dim3 grid(CHUNKS, BQ);
    rows_kernel<<<grid, NTH>>>(seg, det_boxes, det_conf);
    combine_kernel<<<BQ, NTH>>>(det_boxes, det_conf);
    final_kernel<<<1, 32>>>(out);
}